// round 13
// baseline (speedup 1.0000x reference)
#include <cuda_runtime.h>
#include <cuda_bf16.h>
#include <math.h>
#include <stdint.h>

// Problem dims
#define BB 256
#define FF 128
#define QQ 4096
#define EE 128
#define TAU_F 0.2f

// Output layout (float32 concat of reference outputs)
#define OUT_MOCO      0L
#define OUT_LOGITS    1L                       // B x 4097
#define OUT_EASY_LOSS (1L + 256L*4097L)        // 1048833
#define OUT_EASY_MASK (OUT_EASY_LOSS + 1L)     // 1048834, B x Q
#define OUT_HARD_LOSS (OUT_EASY_MASK + 256L*4096L)  // 2097410
#define OUT_HARD_MASK (OUT_HARD_LOSS + 1L)     // 2097411, B x Q
#define OUT_TOTAL     (OUT_HARD_MASK + 256L*4096L)  // 3145987

// -------- device scratch (no allocations allowed) --------
__device__ float g_sim[(size_t)EE * BB * QQ];   // 512 MB
__device__ float g_t[(size_t)EE * BB * FF];     // normalized teacher
__device__ float g_rn[EE * QQ];                 // denominator max(norm,1e-12) for n
__device__ float g_scores[BB * QQ];
__device__ float g_part[EE * QQ];               // per-(e,q) ent/cnt
__device__ float g_unc[QQ];
__device__ float g_thresh;
__device__ float g_lseneg[BB];
__device__ float g_moco[BB];
__device__ float g_easyb[BB];
__device__ float g_hardb[BB];
__device__ int   g_maskmode;                    // 0=u8 1=int32 2=f32 3=bf16

// -------- mask accessor (mode uniform per launch) --------
__device__ __forceinline__ bool MRD(const void* p, size_t i, int mode) {
    if (mode == 0) return ((const uint8_t*)p)[i] != 0;
    if (mode == 1) return ((const int*)p)[i] != 0;
    if (mode == 2) return ((const float*)p)[i] != 0.0f;
    return ((const uint16_t*)p)[i] != 0;
}

// -------- mask storage-dtype detection ----
// int32 bools: words all in {0,1}. fp32: {0, 0x3F800000}. bf16: adds
// 0x00003F80 / 0x3F803F80 patterns. u8: words with 0/1 bytes beyond byte0
// (e.g. 0x00000101). Anything else unexpected -> u8 fallback.
__global__ void k_detect(const uint32_t* __restrict__ w) {
    __shared__ int s_u8, s_bf, s_f32;
    if (threadIdx.x == 0) { s_u8 = 0; s_bf = 0; s_f32 = 0; }
    __syncthreads();
    for (int i = threadIdx.x; i < 8192; i += 256) {
        uint32_t v = w[i];
        if (v == 0u || v == 1u) continue;
        else if (v == 0x3F800000u) s_f32 = 1;
        else if (v == 0x3F803F80u || v == 0x00003F80u) s_bf = 1;
        else s_u8 = 1;
    }
    __syncthreads();
    if (threadIdx.x == 0) {
        int mode;
        if (s_u8) mode = 0;
        else if (s_bf) mode = 3;
        else if (s_f32) mode = 2;
        else mode = 1;
        g_maskmode = mode;
    }
}

// -------- helpers --------
__device__ __forceinline__ float warpSum(float v) {
#pragma unroll
    for (int o = 16; o > 0; o >>= 1) v += __shfl_xor_sync(0xffffffffu, v, o);
    return v;
}
__device__ __forceinline__ float warpMax(float v) {
#pragma unroll
    for (int o = 16; o > 0; o >>= 1) v = fmaxf(v, __shfl_xor_sync(0xffffffffu, v, o));
    return v;
}

// -------- K_fill: zero mask regions ----
__global__ void k_fill(float* __restrict__ out, long n) {
    long i = (long)blockIdx.x * blockDim.x + threadIdx.x;
    if (i < n) out[i] = 0.0f;
}

// -------- K0: logits_neg = (query @ negatives)/TAU -> d_out logits[:,1:] ----
__global__ void k_neglogits(const float* __restrict__ query,
                            const float* __restrict__ negs,
                            float* __restrict__ out) {
    __shared__ float qs[8][128];
    int tx = threadIdx.x;                     // 256
    int qg = blockIdx.x * 256 + tx;
    int b0 = blockIdx.y * 8;
    for (int i = tx; i < 8 * 128; i += 256)
        qs[i >> 7][i & 127] = query[(b0 + (i >> 7)) * 128 + (i & 127)];
    __syncthreads();
    float acc[8];
#pragma unroll
    for (int i = 0; i < 8; i++) acc[i] = 0.0f;
    for (int f = 0; f < 128; f++) {
        float nv = negs[f * QQ + qg];
#pragma unroll
        for (int i = 0; i < 8; i++) acc[i] = fmaf(qs[i][f], nv, acc[i]);
    }
#pragma unroll
    for (int i = 0; i < 8; i++)
        out[OUT_LOGITS + (size_t)(b0 + i) * 4097 + 1 + qg] =
            __fdiv_rn(acc[i], TAU_F);
}

// -------- K0b: pos logit, per-row LSE (neg + full), moco partial ----
__global__ void k_rowstats(const float* __restrict__ query,
                           const float* __restrict__ key,
                           float* __restrict__ out) {
    int b = blockIdx.x, t = threadIdx.x;      // 256 threads
    __shared__ float red[8];
    __shared__ float sh;
    float pp = 0.0f;
    if (t < 128) pp = query[b * 128 + t] * key[b * 128 + t];
    float ws = warpSum(pp);
    if ((t & 31) == 0) red[t >> 5] = ws;
    __syncthreads();
    if (t == 0) {
        float s = 0.0f;
        for (int i = 0; i < 8; i++) s += red[i];
        sh = __fdiv_rn(s, TAU_F);
        out[OUT_LOGITS + (size_t)b * 4097] = sh;
    }
    __syncthreads();
    float pos = sh;
    __syncthreads();
    const float* row = out + OUT_LOGITS + (size_t)b * 4097 + 1;
    float v[16];
#pragma unroll
    for (int k = 0; k < 16; k++) v[k] = row[t + k * 256];
    float m = v[0];
#pragma unroll
    for (int k = 1; k < 16; k++) m = fmaxf(m, v[k]);
    float wm = warpMax(m);
    if ((t & 31) == 0) red[t >> 5] = wm;
    __syncthreads();
    if (t == 0) {
        float mm = red[0];
        for (int i = 1; i < 8; i++) mm = fmaxf(mm, red[i]);
        sh = mm;
    }
    __syncthreads();
    float M = sh;
    __syncthreads();
    float s = 0.0f;
#pragma unroll
    for (int k = 0; k < 16; k++) s += expf(v[k] - M);
    ws = warpSum(s);
    if ((t & 31) == 0) red[t >> 5] = ws;
    __syncthreads();
    if (t == 0) {
        float Sn = 0.0f;
        for (int i = 0; i < 8; i++) Sn += red[i];
        float lse_neg = M + logf(Sn);
        float Mf = fmaxf(M, pos);
        float Sf = Sn * expf(M - Mf) + expf(pos - Mf);
        float lse_full = Mf + logf(Sf);
        g_lseneg[b] = lse_neg;
        g_moco[b] = lse_full - pos;
    }
}

// -------- K1: t = l2norm(mask_t ? 0 : teacher, axis=f) ----
__global__ void k_tnorm(const float* __restrict__ teacher,
                        const void* __restrict__ mask_t) {
    int row = blockIdx.x * blockDim.x + threadIdx.x;   // e*256+b
    if (row >= EE * BB) return;
    int mode = g_maskmode;
    int b = row & 255;
    size_t mbase = (size_t)row * 128;
    const float* trow = teacher + b * 128;
    float p0 = 0.f, p1 = 0.f, p2 = 0.f, p3 = 0.f;
    for (int i = 0; i < 32; i++) {
        float4 v = reinterpret_cast<const float4*>(trow)[i];
        float a0 = MRD(mask_t, mbase + i * 4 + 0, mode) ? 0.0f : v.x;
        float a1 = MRD(mask_t, mbase + i * 4 + 1, mode) ? 0.0f : v.y;
        float a2 = MRD(mask_t, mbase + i * 4 + 2, mode) ? 0.0f : v.z;
        float a3 = MRD(mask_t, mbase + i * 4 + 3, mode) ? 0.0f : v.w;
        p0 = __fadd_rn(p0, __fmul_rn(a0, a0));
        p1 = __fadd_rn(p1, __fmul_rn(a1, a1));
        p2 = __fadd_rn(p2, __fmul_rn(a2, a2));
        p3 = __fadd_rn(p3, __fmul_rn(a3, a3));
    }
    float ss = __fadd_rn(__fadd_rn(p0, p1), __fadd_rn(p2, p3));
    float dn = fmaxf(sqrtf(ss), 1e-12f);
    float* dst = g_t + (size_t)row * 128;
    for (int i = 0; i < 32; i++) {
        float4 v = reinterpret_cast<const float4*>(trow)[i];
        float4 o;
        o.x = __fdiv_rn(MRD(mask_t, mbase + i * 4 + 0, mode) ? 0.0f : v.x, dn);
        o.y = __fdiv_rn(MRD(mask_t, mbase + i * 4 + 1, mode) ? 0.0f : v.y, dn);
        o.z = __fdiv_rn(MRD(mask_t, mbase + i * 4 + 2, mode) ? 0.0f : v.z, dn);
        o.w = __fdiv_rn(MRD(mask_t, mbase + i * 4 + 3, mode) ? 0.0f : v.w, dn);
        reinterpret_cast<float4*>(dst)[i] = o;
    }
}

// -------- K1b: denom over f of (mask_n ? 0 : negatives) per (e,q) ----
__global__ void k_rnorm(const float* __restrict__ negs,
                        const void* __restrict__ mask_n) {
    int qg = blockIdx.x * 256 + threadIdx.x;
    int e = blockIdx.y;
    int mode = g_maskmode;
    float ss = 0.0f;
    for (int f = 0; f < 128; f++) {
        bool m = MRD(mask_n, ((size_t)e * 128 + f) * QQ + qg, mode);
        float v = m ? 0.0f : negs[f * QQ + qg];
        ss = __fadd_rn(ss, __fmul_rn(v, v));
    }
    g_rn[e * QQ + qg] = fmaxf(sqrtf(ss), 1e-12f);
}

// -------- K2: sim[e] = (t[e] @ n[e]) / TAU, 128x128 tiles, K=128 ----
__global__ void k_gemm(const float* __restrict__ negs,
                       const void* __restrict__ mask_n) {
    extern __shared__ float sm[];
    float* As = sm;               // [128][132] transposed (k-major)
    float* Bs = sm + 128 * 132;   // [128][128] k-major
    int e = blockIdx.z;
    int mb = blockIdx.x * 128;
    int qb = blockIdx.y * 128;
    int tid = threadIdx.x;        // 256
    int mode = g_maskmode;

    const float* Ag = g_t + ((size_t)e * 256 + mb) * 128;
    for (int i = tid; i < 16384; i += 256) {
        int m = i >> 7, f = i & 127;
        As[f * 132 + m] = Ag[m * 128 + f];
    }
    float dn_local = g_rn[e * QQ + qb + (tid & 127)];
    for (int i = tid; i < 16384; i += 256) {
        int f = i >> 7, q = i & 127;
        int qg = qb + q;
        bool mk = MRD(mask_n, ((size_t)e * 128 + f) * QQ + qg, mode);
        Bs[f * 128 + q] = mk ? 0.0f : __fdiv_rn(negs[f * QQ + qg], dn_local);
    }
    __syncthreads();

    int tx = tid & 15, ty = tid >> 4;
    float acc[8][8];
#pragma unroll
    for (int i = 0; i < 8; i++)
#pragma unroll
        for (int j = 0; j < 8; j++) acc[i][j] = 0.0f;

#pragma unroll 8
    for (int k = 0; k < 128; k++) {
        float4 a0 = *reinterpret_cast<const float4*>(&As[k * 132 + ty * 8]);
        float4 a1 = *reinterpret_cast<const float4*>(&As[k * 132 + ty * 8 + 4]);
        float4 b0 = *reinterpret_cast<const float4*>(&Bs[k * 128 + tx * 8]);
        float4 b1 = *reinterpret_cast<const float4*>(&Bs[k * 128 + tx * 8 + 4]);
        float a[8] = {a0.x, a0.y, a0.z, a0.w, a1.x, a1.y, a1.z, a1.w};
        float bv[8] = {b0.x, b0.y, b0.z, b0.w, b1.x, b1.y, b1.z, b1.w};
#pragma unroll
        for (int i = 0; i < 8; i++)
#pragma unroll
            for (int j = 0; j < 8; j++) acc[i][j] = fmaf(a[i], bv[j], acc[i][j]);
    }

#pragma unroll
    for (int i = 0; i < 8; i++) {
        size_t row = (size_t)e * 256 + mb + ty * 8 + i;
        float* dst = g_sim + row * QQ + qb + tx * 8;
        float4 o0, o1;
        o0.x = __fdiv_rn(acc[i][0], TAU_F);
        o0.y = __fdiv_rn(acc[i][1], TAU_F);
        o0.z = __fdiv_rn(acc[i][2], TAU_F);
        o0.w = __fdiv_rn(acc[i][3], TAU_F);
        o1.x = __fdiv_rn(acc[i][4], TAU_F);
        o1.y = __fdiv_rn(acc[i][5], TAU_F);
        o1.z = __fdiv_rn(acc[i][6], TAU_F);
        o1.w = __fdiv_rn(acc[i][7], TAU_F);
        *reinterpret_cast<float4*>(dst) = o0;
        *reinterpret_cast<float4*>(dst + 4) = o1;
    }
}

// -------- K3: scores[b,q] = (sum_e masked_softmax_Q(sim)[e,b,q]) / cnt_e ----
__global__ void k_scores(const void* __restrict__ smask) {
    int b = blockIdx.x, t = threadIdx.x;      // 512 threads
    __shared__ float redf[16];
    __shared__ float shf;
    int mode = g_maskmode;
    float acc[8];
    int cnt[8];
#pragma unroll
    for (int k = 0; k < 8; k++) { acc[k] = 0.0f; cnt[k] = 0; }

    for (int e = 0; e < EE; e++) {
        size_t base = ((size_t)e * 256 + b) * QQ;
        float v[8];
        bool mk[8];
#pragma unroll
        for (int k = 0; k < 8; k++) {
            int q = t + k * 512;
            v[k] = g_sim[base + q];
            mk[k] = MRD(smask, base + q, mode);
        }
        float m = -INFINITY;
#pragma unroll
        for (int k = 0; k < 8; k++) if (mk[k]) m = fmaxf(m, v[k]);
        float wm = warpMax(m);
        if ((t & 31) == 0) redf[t >> 5] = wm;
        __syncthreads();
        if (t == 0) {
            float mm = -INFINITY;
            for (int i = 0; i < 16; i++) mm = fmaxf(mm, redf[i]);
            shf = mm;
        }
        __syncthreads();
        float M = shf;
        __syncthreads();
        if (M == -INFINITY) continue;   // no sampled entry in this (e,b) row
        float ek[8];
        float s = 0.0f;
#pragma unroll
        for (int k = 0; k < 8; k++) {
            ek[k] = mk[k] ? expf(v[k] - M) : 0.0f;
            s += ek[k];
        }
        float wsv = warpSum(s);
        if ((t & 31) == 0) redf[t >> 5] = wsv;
        __syncthreads();
        if (t == 0) {
            float ss = 0.0f;
            for (int i = 0; i < 16; i++) ss += redf[i];
            shf = ss;
        }
        __syncthreads();
        float S = fmaxf(shf, 1e-30f);
        __syncthreads();
#pragma unroll
        for (int k = 0; k < 8; k++) {
            if (mk[k]) {
                acc[k] = __fadd_rn(acc[k], __fdiv_rn(ek[k], S));
                cnt[k] += 1;
            }
        }
    }
#pragma unroll
    for (int k = 0; k < 8; k++) {
        int q = t + k * 512;
        float c = fmaxf((float)cnt[k], 1.0f);
        g_scores[b * QQ + q] = __fdiv_rn(acc[k], c);
    }
}

// -------- K4: per-(e,q) masked entropy over B — fp32 reference order ----
__global__ void k_unc(const void* __restrict__ boot) {
    int qg = blockIdx.x * 256 + threadIdx.x;
    int e = blockIdx.y;
    int mode = g_maskmode;
    size_t base = ((size_t)e * 256) * QQ + qg;

    float m = -INFINITY;
    int cnt = 0;
    for (int b = 0; b < 256; b++) {
        size_t idx = base + (size_t)b * QQ;
        if (MRD(boot, idx, mode)) { cnt++; m = fmaxf(m, g_sim[idx]); }
    }
    float S = 0.0f;
    for (int b = 0; b < 256; b++) {
        size_t idx = base + (size_t)b * QQ;
        if (MRD(boot, idx, mode)) S = __fadd_rn(S, expf(g_sim[idx] - m));
    }
    S = fmaxf(S, 1e-30f);

    const float EPS = 1e-7f;
    float negc0 = -(__fmul_rn(EPS, logf(EPS)));
    float ent = 0.0f;
    for (int b = 0; b < 256; b++) {
        size_t idx = base + (size_t)b * QQ;
        float term;
        if (MRD(boot, idx, mode)) {
            float p = __fadd_rn(__fdiv_rn(expf(g_sim[idx] - m), S), EPS);
            term = -(__fmul_rn(p, logf(p)));
        } else {
            term = negc0;
        }
        ent = __fadd_rn(ent, term);
    }
    g_part[e * QQ + qg] = __fdiv_rn(ent, fmaxf((float)cnt, 1.0f));
}

// -------- K5a: uncertainty[q] = mean_e g_part (fp32 seq-e) ----
__global__ void k_ereduce() {
    int q = blockIdx.x * 256 + threadIdx.x;
    float s = 0.0f;
    for (int e = 0; e < EE; e++) s = __fadd_rn(s, g_part[e * QQ + q]);
    g_unc[q] = s / 128.0f;   // /128 exact (power of 2)
}

// -------- K5b: median threshold (jnp.quantile 0.5 linear) via rank count ----
__global__ void k_quant() {
    __shared__ float u[QQ];
    __shared__ float res[2];
    int t = threadIdx.x;                 // 1024
    for (int i = t; i < QQ; i += 1024) u[i] = g_unc[i];
    __syncthreads();
    for (int i = t; i < QQ; i += 1024) {
        float v = u[i];
        int cl = 0, ce = 0;
        for (int j = 0; j < QQ; j++) {
            float x = u[j];
            cl += (x < v) ? 1 : 0;
            ce += (x == v) ? 1 : 0;
        }
        if (cl <= 2047 && 2047 < cl + ce) res[0] = v;
        if (cl <= 2048 && 2048 < cl + ce) res[1] = v;
    }
    __syncthreads();
    if (t == 0) {
        float a = res[0], bqv = res[1];
        // jnp 'linear': a + (b-a)*0.5, mirrored in fp32
        g_thresh = __fadd_rn(a, __fmul_rn(__fsub_rn(bqv, a), 0.5f));
    }
}

// -------- K6: per-b argmax over allowed q (easy: u<=thr, hard: u>=thr) ----
__global__ void k_argmax(float* __restrict__ out) {
    int b = blockIdx.x, t = threadIdx.x;   // 256
    __shared__ float sv[256];
    __shared__ int si[256];
    float thr = g_thresh;
    const float* srow = g_scores + (size_t)b * QQ;

    for (int pass = 0; pass < 2; pass++) {
        float bv = -INFINITY;
        int bi = 0x7fffffff;
#pragma unroll 4
        for (int k = 0; k < 16; k++) {
            int q = t + k * 256;
            float u = g_unc[q];
            bool ok = pass == 0 ? (u <= thr) : (u >= thr);
            if (ok) {
                float sc = srow[q];
                if (sc > bv || (sc == bv && q < bi)) { bv = sc; bi = q; }
            }
        }
        sv[t] = bv; si[t] = bi;
        __syncthreads();
        for (int s2 = 128; s2 > 0; s2 >>= 1) {
            if (t < s2) {
                float ov = sv[t + s2]; int oi = si[t + s2];
                if (ov > sv[t] || (ov == sv[t] && oi < si[t])) { sv[t] = ov; si[t] = oi; }
            }
            __syncthreads();
        }
        if (t == 0) {
            int idx = si[0];
            float L = out[OUT_LOGITS + (size_t)b * 4097 + 1 + idx];
            float loss = -(L - g_lseneg[b]);
            if (pass == 0) {
                g_easyb[b] = loss;
                out[OUT_EASY_MASK + (size_t)b * QQ + idx] = 1.0f;
            } else {
                g_hardb[b] = loss;
                out[OUT_HARD_MASK + (size_t)b * QQ + idx] = 1.0f;
            }
        }
        __syncthreads();
    }
}

// -------- K7: final scalar reductions ----
__global__ void k_final(float* __restrict__ out) {
    int t = threadIdx.x;                   // 256
    __shared__ float red[8];
    float vm = g_moco[t], ve = g_easyb[t], vh = g_hardb[t];

    float s = warpSum(vm);
    if ((t & 31) == 0) red[t >> 5] = s;
    __syncthreads();
    if (t == 0) {
        float x = 0.0f; for (int i = 0; i < 8; i++) x += red[i];
        out[OUT_MOCO] = x / 256.0f;
    }
    __syncthreads();
    s = warpSum(ve);
    if ((t & 31) == 0) red[t >> 5] = s;
    __syncthreads();
    if (t == 0) {
        float x = 0.0f; for (int i = 0; i < 8; i++) x += red[i];
        out[OUT_EASY_LOSS] = x / 256.0f;
    }
    __syncthreads();
    s = warpSum(vh);
    if ((t & 31) == 0) red[t >> 5] = s;
    __syncthreads();
    if (t == 0) {
        float x = 0.0f; for (int i = 0; i < 8; i++) x += red[i];
        out[OUT_HARD_LOSS] = x / 256.0f;
    }
}

// ===================== launch =====================
extern "C" void kernel_launch(void* const* d_in, const int* in_sizes, int n_in,
                              void* d_out, int out_size) {
    const float* query   = (const float*)d_in[0];
    const float* key     = (const float*)d_in[1];
    const float* teacher = (const float*)d_in[2];
    const float* negs    = (const float*)d_in[3];
    const void*  mask_t  = d_in[4];
    const void*  mask_n  = d_in[5];
    const void*  smask   = d_in[6];
    const void*  boot    = d_in[7];
    float* out = (float*)d_out;
    (void)in_sizes; (void)n_in; (void)out_size;

    k_detect<<<1, 256>>>((const uint32_t*)mask_t);

    {
        long n = OUT_TOTAL - OUT_EASY_MASK;
        int grid = (int)((n + 1023) / 1024);
        k_fill<<<grid, 1024>>>(out + OUT_EASY_MASK, n);
    }

    k_neglogits<<<dim3(QQ / 256, BB / 8), 256>>>(query, negs, out);
    k_rowstats<<<BB, 256>>>(query, key, out);
    k_tnorm<<<(EE * BB) / 256, 256>>>(teacher, mask_t);
    k_rnorm<<<dim3(QQ / 256, EE), 256>>>(negs, mask_n);

    static const int SMEM_BYTES = (128 * 132 + 128 * 128) * 4;
    cudaFuncSetAttribute(k_gemm, cudaFuncAttributeMaxDynamicSharedMemorySize,
                         SMEM_BYTES);
    k_gemm<<<dim3(BB / 128, QQ / 128, EE), 256, SMEM_BYTES>>>(negs, mask_n);

    k_scores<<<BB, 512>>>(smask);
    k_unc<<<dim3(QQ / 256, EE), 256>>>(boot);
    k_ereduce<<<QQ / 256, 256>>>();
    k_quant<<<1, 1024>>>();
    k_argmax<<<BB, 256>>>(out);
    k_final<<<1, 256>>>(out);
}

// round 14
// speedup vs baseline: 1.1550x; 1.1550x over previous
#include <cuda_runtime.h>
#include <cuda_bf16.h>
#include <math.h>
#include <stdint.h>

// Problem dims
#define BB 256
#define FF 128
#define QQ 4096
#define EE 128
#define TAU_F 0.2f

// Output layout (float32 concat of reference outputs)
#define OUT_MOCO      0L
#define OUT_LOGITS    1L                       // B x 4097
#define OUT_EASY_LOSS (1L + 256L*4097L)        // 1048833
#define OUT_EASY_MASK (OUT_EASY_LOSS + 1L)     // 1048834, B x Q
#define OUT_HARD_LOSS (OUT_EASY_MASK + 256L*4096L)  // 2097410
#define OUT_HARD_MASK (OUT_HARD_LOSS + 1L)     // 2097411, B x Q
#define OUT_TOTAL     (OUT_HARD_MASK + 256L*4096L)  // 3145987

// -------- device scratch (no allocations allowed) --------
__device__ float g_sim[(size_t)EE * BB * QQ];   // 512 MB
__device__ float g_t[(size_t)EE * BB * FF];     // normalized teacher
__device__ float g_rn[EE * QQ];                 // denominator max(norm,1e-12) for n
__device__ float g_scores[BB * QQ];
__device__ float g_part[EE * QQ];               // per-(e,q) ent/cnt
__device__ float g_unc[QQ];
__device__ float g_res2[2];
__device__ float g_thresh;
__device__ float g_lseneg[BB];
__device__ float g_moco[BB];
__device__ float g_easyb[BB];
__device__ float g_hardb[BB];
__device__ int   g_maskmode;                    // 0=u8 1=int32 2=f32 3=bf16

// -------- mask accessor (mode uniform per launch) --------
__device__ __forceinline__ bool MRD(const void* p, size_t i, int mode) {
    if (mode == 0) return ((const uint8_t*)p)[i] != 0;
    if (mode == 1) return ((const int*)p)[i] != 0;
    if (mode == 2) return ((const float*)p)[i] != 0.0f;
    return ((const uint16_t*)p)[i] != 0;
}

// -------- mask storage-dtype detection ----
__global__ void k_detect(const uint32_t* __restrict__ w) {
    __shared__ int s_u8, s_bf, s_f32;
    if (threadIdx.x == 0) { s_u8 = 0; s_bf = 0; s_f32 = 0; }
    __syncthreads();
    for (int i = threadIdx.x; i < 8192; i += 256) {
        uint32_t v = w[i];
        if (v == 0u || v == 1u) continue;
        else if (v == 0x3F800000u) s_f32 = 1;
        else if (v == 0x3F803F80u || v == 0x00003F80u) s_bf = 1;
        else s_u8 = 1;
    }
    __syncthreads();
    if (threadIdx.x == 0) {
        int mode;
        if (s_u8) mode = 0;
        else if (s_bf) mode = 3;
        else if (s_f32) mode = 2;
        else mode = 1;
        g_maskmode = mode;
    }
}

// -------- helpers --------
__device__ __forceinline__ float warpSum(float v) {
#pragma unroll
    for (int o = 16; o > 0; o >>= 1) v += __shfl_xor_sync(0xffffffffu, v, o);
    return v;
}
__device__ __forceinline__ float warpMax(float v) {
#pragma unroll
    for (int o = 16; o > 0; o >>= 1) v = fmaxf(v, __shfl_xor_sync(0xffffffffu, v, o));
    return v;
}

// -------- K_fill: zero mask regions ----
__global__ void k_fill(float* __restrict__ out, long n) {
    long i = (long)blockIdx.x * blockDim.x + threadIdx.x;
    if (i < n) out[i] = 0.0f;
}

// -------- K0: logits_neg = (query @ negatives)/TAU -> d_out logits[:,1:] ----
__global__ void k_neglogits(const float* __restrict__ query,
                            const float* __restrict__ negs,
                            float* __restrict__ out) {
    __shared__ float qs[8][128];
    int tx = threadIdx.x;                     // 256
    int qg = blockIdx.x * 256 + tx;
    int b0 = blockIdx.y * 8;
    for (int i = tx; i < 8 * 128; i += 256)
        qs[i >> 7][i & 127] = query[(b0 + (i >> 7)) * 128 + (i & 127)];
    __syncthreads();
    float acc[8];
#pragma unroll
    for (int i = 0; i < 8; i++) acc[i] = 0.0f;
    for (int f = 0; f < 128; f++) {
        float nv = negs[f * QQ + qg];
#pragma unroll
        for (int i = 0; i < 8; i++) acc[i] = fmaf(qs[i][f], nv, acc[i]);
    }
#pragma unroll
    for (int i = 0; i < 8; i++)
        out[OUT_LOGITS + (size_t)(b0 + i) * 4097 + 1 + qg] =
            __fdiv_rn(acc[i], TAU_F);
}

// -------- K0b: pos logit, per-row LSE (neg + full), moco partial ----
__global__ void k_rowstats(const float* __restrict__ query,
                           const float* __restrict__ key,
                           float* __restrict__ out) {
    int b = blockIdx.x, t = threadIdx.x;      // 256 threads
    __shared__ float red[8];
    __shared__ float sh;
    float pp = 0.0f;
    if (t < 128) pp = query[b * 128 + t] * key[b * 128 + t];
    float ws = warpSum(pp);
    if ((t & 31) == 0) red[t >> 5] = ws;
    __syncthreads();
    if (t == 0) {
        float s = 0.0f;
        for (int i = 0; i < 8; i++) s += red[i];
        sh = __fdiv_rn(s, TAU_F);
        out[OUT_LOGITS + (size_t)b * 4097] = sh;
    }
    __syncthreads();
    float pos = sh;
    __syncthreads();
    const float* row = out + OUT_LOGITS + (size_t)b * 4097 + 1;
    float v[16];
#pragma unroll
    for (int k = 0; k < 16; k++) v[k] = row[t + k * 256];
    float m = v[0];
#pragma unroll
    for (int k = 1; k < 16; k++) m = fmaxf(m, v[k]);
    float wm = warpMax(m);
    if ((t & 31) == 0) red[t >> 5] = wm;
    __syncthreads();
    if (t == 0) {
        float mm = red[0];
        for (int i = 1; i < 8; i++) mm = fmaxf(mm, red[i]);
        sh = mm;
    }
    __syncthreads();
    float M = sh;
    __syncthreads();
    float s = 0.0f;
#pragma unroll
    for (int k = 0; k < 16; k++) s += expf(v[k] - M);
    ws = warpSum(s);
    if ((t & 31) == 0) red[t >> 5] = ws;
    __syncthreads();
    if (t == 0) {
        float Sn = 0.0f;
        for (int i = 0; i < 8; i++) Sn += red[i];
        float lse_neg = M + logf(Sn);
        float Mf = fmaxf(M, pos);
        float Sf = Sn * expf(M - Mf) + expf(pos - Mf);
        float lse_full = Mf + logf(Sf);
        g_lseneg[b] = lse_neg;
        g_moco[b] = lse_full - pos;
    }
}

// -------- K1: t = l2norm(mask_t ? 0 : teacher, axis=f) ----
__global__ void k_tnorm(const float* __restrict__ teacher,
                        const void* __restrict__ mask_t) {
    int row = blockIdx.x * blockDim.x + threadIdx.x;   // e*256+b
    if (row >= EE * BB) return;
    int mode = g_maskmode;
    int b = row & 255;
    size_t mbase = (size_t)row * 128;
    const float* trow = teacher + b * 128;
    float p0 = 0.f, p1 = 0.f, p2 = 0.f, p3 = 0.f;
    for (int i = 0; i < 32; i++) {
        float4 v = reinterpret_cast<const float4*>(trow)[i];
        float a0 = MRD(mask_t, mbase + i * 4 + 0, mode) ? 0.0f : v.x;
        float a1 = MRD(mask_t, mbase + i * 4 + 1, mode) ? 0.0f : v.y;
        float a2 = MRD(mask_t, mbase + i * 4 + 2, mode) ? 0.0f : v.z;
        float a3 = MRD(mask_t, mbase + i * 4 + 3, mode) ? 0.0f : v.w;
        p0 = __fadd_rn(p0, __fmul_rn(a0, a0));
        p1 = __fadd_rn(p1, __fmul_rn(a1, a1));
        p2 = __fadd_rn(p2, __fmul_rn(a2, a2));
        p3 = __fadd_rn(p3, __fmul_rn(a3, a3));
    }
    float ss = __fadd_rn(__fadd_rn(p0, p1), __fadd_rn(p2, p3));
    float dn = fmaxf(sqrtf(ss), 1e-12f);
    float* dst = g_t + (size_t)row * 128;
    for (int i = 0; i < 32; i++) {
        float4 v = reinterpret_cast<const float4*>(trow)[i];
        float4 o;
        o.x = __fdiv_rn(MRD(mask_t, mbase + i * 4 + 0, mode) ? 0.0f : v.x, dn);
        o.y = __fdiv_rn(MRD(mask_t, mbase + i * 4 + 1, mode) ? 0.0f : v.y, dn);
        o.z = __fdiv_rn(MRD(mask_t, mbase + i * 4 + 2, mode) ? 0.0f : v.z, dn);
        o.w = __fdiv_rn(MRD(mask_t, mbase + i * 4 + 3, mode) ? 0.0f : v.w, dn);
        reinterpret_cast<float4*>(dst)[i] = o;
    }
}

// -------- K1b: denom over f of (mask_n ? 0 : negatives) per (e,q) ----
__global__ void k_rnorm(const float* __restrict__ negs,
                        const void* __restrict__ mask_n) {
    int qg = blockIdx.x * 256 + threadIdx.x;
    int e = blockIdx.y;
    int mode = g_maskmode;
    float ss = 0.0f;
    for (int f = 0; f < 128; f++) {
        bool m = MRD(mask_n, ((size_t)e * 128 + f) * QQ + qg, mode);
        float v = m ? 0.0f : negs[f * QQ + qg];
        ss = __fadd_rn(ss, __fmul_rn(v, v));
    }
    g_rn[e * QQ + qg] = fmaxf(sqrtf(ss), 1e-12f);
}

// -------- K2: sim[e] = (t[e] @ n[e]) / TAU, 128x128 tiles, K=128 ----
__global__ void k_gemm(const float* __restrict__ negs,
                       const void* __restrict__ mask_n) {
    extern __shared__ float sm[];
    float* As = sm;               // [128][132] transposed (k-major)
    float* Bs = sm + 128 * 132;   // [128][128] k-major
    int e = blockIdx.z;
    int mb = blockIdx.x * 128;
    int qb = blockIdx.y * 128;
    int tid = threadIdx.x;        // 256
    int mode = g_maskmode;

    const float* Ag = g_t + ((size_t)e * 256 + mb) * 128;
    for (int i = tid; i < 16384; i += 256) {
        int m = i >> 7, f = i & 127;
        As[f * 132 + m] = Ag[m * 128 + f];
    }
    float dn_local = g_rn[e * QQ + qb + (tid & 127)];
    for (int i = tid; i < 16384; i += 256) {
        int f = i >> 7, q = i & 127;
        int qg = qb + q;
        bool mk = MRD(mask_n, ((size_t)e * 128 + f) * QQ + qg, mode);
        Bs[f * 128 + q] = mk ? 0.0f : __fdiv_rn(negs[f * QQ + qg], dn_local);
    }
    __syncthreads();

    int tx = tid & 15, ty = tid >> 4;
    float acc[8][8];
#pragma unroll
    for (int i = 0; i < 8; i++)
#pragma unroll
        for (int j = 0; j < 8; j++) acc[i][j] = 0.0f;

#pragma unroll 8
    for (int k = 0; k < 128; k++) {
        float4 a0 = *reinterpret_cast<const float4*>(&As[k * 132 + ty * 8]);
        float4 a1 = *reinterpret_cast<const float4*>(&As[k * 132 + ty * 8 + 4]);
        float4 b0 = *reinterpret_cast<const float4*>(&Bs[k * 128 + tx * 8]);
        float4 b1 = *reinterpret_cast<const float4*>(&Bs[k * 128 + tx * 8 + 4]);
        float a[8] = {a0.x, a0.y, a0.z, a0.w, a1.x, a1.y, a1.z, a1.w};
        float bv[8] = {b0.x, b0.y, b0.z, b0.w, b1.x, b1.y, b1.z, b1.w};
#pragma unroll
        for (int i = 0; i < 8; i++)
#pragma unroll
            for (int j = 0; j < 8; j++) acc[i][j] = fmaf(a[i], bv[j], acc[i][j]);
    }

#pragma unroll
    for (int i = 0; i < 8; i++) {
        size_t row = (size_t)e * 256 + mb + ty * 8 + i;
        float* dst = g_sim + row * QQ + qb + tx * 8;
        float4 o0, o1;
        o0.x = __fdiv_rn(acc[i][0], TAU_F);
        o0.y = __fdiv_rn(acc[i][1], TAU_F);
        o0.z = __fdiv_rn(acc[i][2], TAU_F);
        o0.w = __fdiv_rn(acc[i][3], TAU_F);
        o1.x = __fdiv_rn(acc[i][4], TAU_F);
        o1.y = __fdiv_rn(acc[i][5], TAU_F);
        o1.z = __fdiv_rn(acc[i][6], TAU_F);
        o1.w = __fdiv_rn(acc[i][7], TAU_F);
        *reinterpret_cast<float4*>(dst) = o0;
        *reinterpret_cast<float4*>(dst + 4) = o1;
    }
}

// -------- K3: scores[b,q] = (sum_e masked_softmax_Q(sim)[e,b,q]) / cnt_e ----
// thread-0 serial reductions kept byte-identical; barriers reduced 6 -> 4 per e
__global__ void k_scores(const void* __restrict__ smask) {
    int b = blockIdx.x, t = threadIdx.x;      // 512 threads
    __shared__ float redf[16];
    __shared__ float shM;
    __shared__ float shS;
    int mode = g_maskmode;
    float acc[8];
    int cnt[8];
#pragma unroll
    for (int k = 0; k < 8; k++) { acc[k] = 0.0f; cnt[k] = 0; }

    for (int e = 0; e < EE; e++) {
        size_t base = ((size_t)e * 256 + b) * QQ;
        float v[8];
        bool mk[8];
#pragma unroll
        for (int k = 0; k < 8; k++) {
            int q = t + k * 512;
            v[k] = g_sim[base + q];
            mk[k] = MRD(smask, base + q, mode);
        }
        float m = -INFINITY;
#pragma unroll
        for (int k = 0; k < 8; k++) if (mk[k]) m = fmaxf(m, v[k]);
        float wm = warpMax(m);
        if ((t & 31) == 0) redf[t >> 5] = wm;
        __syncthreads();                        // (1)
        if (t == 0) {
            float mm = -INFINITY;
            for (int i = 0; i < 16; i++) mm = fmaxf(mm, redf[i]);
            shM = mm;
        }
        __syncthreads();                        // (2)
        float M = shM;
        if (M == -INFINITY) continue;           // uniform across block
        float ek[8];
        float s = 0.0f;
#pragma unroll
        for (int k = 0; k < 8; k++) {
            ek[k] = mk[k] ? expf(v[k] - M) : 0.0f;
            s += ek[k];
        }
        float wsv = warpSum(s);
        if ((t & 31) == 0) redf[t >> 5] = wsv;
        __syncthreads();                        // (3)
        if (t == 0) {
            float ss = 0.0f;
            for (int i = 0; i < 16; i++) ss += redf[i];
            shS = ss;
        }
        __syncthreads();                        // (4)
        float S = fmaxf(shS, 1e-30f);
#pragma unroll
        for (int k = 0; k < 8; k++) {
            if (mk[k]) {
                acc[k] = __fadd_rn(acc[k], __fdiv_rn(ek[k], S));
                cnt[k] += 1;
            }
        }
    }
#pragma unroll
    for (int k = 0; k < 8; k++) {
        int q = t + k * 512;
        float c = fmaxf((float)cnt[k], 1.0f);
        g_scores[b * QQ + q] = __fdiv_rn(acc[k], c);
    }
}

// -------- K4: per-(e,q) masked entropy over B — fp32 reference order ----
// boot mask read from DRAM once (pass 1), cached as 256 bits in registers.
__global__ void k_unc(const void* __restrict__ boot) {
    int qg = blockIdx.x * 256 + threadIdx.x;
    int e = blockIdx.y;
    int mode = g_maskmode;
    size_t base = ((size_t)e * 256) * QQ + qg;

    uint32_t mbits[8];
#pragma unroll
    for (int i = 0; i < 8; i++) mbits[i] = 0u;

    float m = -INFINITY;
    int cnt = 0;
    for (int b = 0; b < 256; b++) {
        size_t idx = base + (size_t)b * QQ;
        bool mk = MRD(boot, idx, mode);
        if (mk) {
            cnt++;
            m = fmaxf(m, g_sim[idx]);
            mbits[b >> 5] |= (1u << (b & 31));
        }
    }
    float S = 0.0f;
    for (int b = 0; b < 256; b++) {
        if ((mbits[b >> 5] >> (b & 31)) & 1u) {
            size_t idx = base + (size_t)b * QQ;
            S = __fadd_rn(S, expf(g_sim[idx] - m));
        }
    }
    S = fmaxf(S, 1e-30f);

    const float EPS = 1e-7f;
    float negc0 = -(__fmul_rn(EPS, logf(EPS)));
    float ent = 0.0f;
    for (int b = 0; b < 256; b++) {
        float term;
        if ((mbits[b >> 5] >> (b & 31)) & 1u) {
            size_t idx = base + (size_t)b * QQ;
            float p = __fadd_rn(__fdiv_rn(expf(g_sim[idx] - m), S), EPS);
            term = -(__fmul_rn(p, logf(p)));
        } else {
            term = negc0;
        }
        ent = __fadd_rn(ent, term);
    }
    g_part[e * QQ + qg] = __fdiv_rn(ent, fmaxf((float)cnt, 1.0f));
}

// -------- K5a: uncertainty[q] = mean_e g_part (fp32 seq-e) ----
__global__ void k_ereduce() {
    int q = blockIdx.x * 256 + threadIdx.x;
    float s = 0.0f;
    for (int e = 0; e < EE; e++) s = __fadd_rn(s, g_part[e * QQ + q]);
    g_unc[q] = s / 128.0f;   // /128 exact (power of 2)
}

// -------- K5b: median rank scan — parallel across 32 blocks ----
// All writers of g_res2[k] hold the same value (the k-th order statistic),
// so racing same-value stores are deterministic.
__global__ void k_quant() {
    __shared__ float u[QQ];
    int t = threadIdx.x;                 // 128
    for (int i = t; i < QQ; i += 128) u[i] = g_unc[i];
    __syncthreads();
    int i = blockIdx.x * 128 + t;        // 32 blocks -> 4096 candidates
    float v = u[i];
    int cl = 0, ce = 0;
    for (int j = 0; j < QQ; j++) {
        float x = u[j];
        cl += (x < v) ? 1 : 0;
        ce += (x == v) ? 1 : 0;
    }
    if (cl <= 2047 && 2047 < cl + ce) g_res2[0] = v;
    if (cl <= 2048 && 2048 < cl + ce) g_res2[1] = v;
}

__global__ void k_quantfin() {
    float a = g_res2[0], bqv = g_res2[1];
    // jnp 'linear': a + (b-a)*0.5, mirrored in fp32
    g_thresh = __fadd_rn(a, __fmul_rn(__fsub_rn(bqv, a), 0.5f));
}

// -------- K6: per-b argmax over allowed q (easy: u<=thr, hard: u>=thr) ----
__global__ void k_argmax(float* __restrict__ out) {
    int b = blockIdx.x, t = threadIdx.x;   // 256
    __shared__ float sv[256];
    __shared__ int si[256];
    float thr = g_thresh;
    const float* srow = g_scores + (size_t)b * QQ;

    for (int pass = 0; pass < 2; pass++) {
        float bv = -INFINITY;
        int bi = 0x7fffffff;
#pragma unroll 4
        for (int k = 0; k < 16; k++) {
            int q = t + k * 256;
            float u = g_unc[q];
            bool ok = pass == 0 ? (u <= thr) : (u >= thr);
            if (ok) {
                float sc = srow[q];
                if (sc > bv || (sc == bv && q < bi)) { bv = sc; bi = q; }
            }
        }
        sv[t] = bv; si[t] = bi;
        __syncthreads();
        for (int s2 = 128; s2 > 0; s2 >>= 1) {
            if (t < s2) {
                float ov = sv[t + s2]; int oi = si[t + s2];
                if (ov > sv[t] || (ov == sv[t] && oi < si[t])) { sv[t] = ov; si[t] = oi; }
            }
            __syncthreads();
        }
        if (t == 0) {
            int idx = si[0];
            float L = out[OUT_LOGITS + (size_t)b * 4097 + 1 + idx];
            float loss = -(L - g_lseneg[b]);
            if (pass == 0) {
                g_easyb[b] = loss;
                out[OUT_EASY_MASK + (size_t)b * QQ + idx] = 1.0f;
            } else {
                g_hardb[b] = loss;
                out[OUT_HARD_MASK + (size_t)b * QQ + idx] = 1.0f;
            }
        }
        __syncthreads();
    }
}

// -------- K7: final scalar reductions ----
__global__ void k_final(float* __restrict__ out) {
    int t = threadIdx.x;                   // 256
    __shared__ float red[8];
    float vm = g_moco[t], ve = g_easyb[t], vh = g_hardb[t];

    float s = warpSum(vm);
    if ((t & 31) == 0) red[t >> 5] = s;
    __syncthreads();
    if (t == 0) {
        float x = 0.0f; for (int i = 0; i < 8; i++) x += red[i];
        out[OUT_MOCO] = x / 256.0f;
    }
    __syncthreads();
    s = warpSum(ve);
    if ((t & 31) == 0) red[t >> 5] = s;
    __syncthreads();
    if (t == 0) {
        float x = 0.0f; for (int i = 0; i < 8; i++) x += red[i];
        out[OUT_EASY_LOSS] = x / 256.0f;
    }
    __syncthreads();
    s = warpSum(vh);
    if ((t & 31) == 0) red[t >> 5] = s;
    __syncthreads();
    if (t == 0) {
        float x = 0.0f; for (int i = 0; i < 8; i++) x += red[i];
        out[OUT_HARD_LOSS] = x / 256.0f;
    }
}

// ===================== launch =====================
// Order chosen so the ncu capture slot (landed on launch #4 last round)
// profiles k_gemm; slot #6 would be k_scores.
extern "C" void kernel_launch(void* const* d_in, const int* in_sizes, int n_in,
                              void* d_out, int out_size) {
    const float* query   = (const float*)d_in[0];
    const float* key     = (const float*)d_in[1];
    const float* teacher = (const float*)d_in[2];
    const float* negs    = (const float*)d_in[3];
    const void*  mask_t  = d_in[4];
    const void*  mask_n  = d_in[5];
    const void*  smask   = d_in[6];
    const void*  boot    = d_in[7];
    float* out = (float*)d_out;
    (void)in_sizes; (void)n_in; (void)out_size;

    k_detect<<<1, 256>>>((const uint32_t*)mask_t);                 // 1
    k_tnorm<<<(EE * BB) / 256, 256>>>(teacher, mask_t);            // 2
    k_rnorm<<<dim3(QQ / 256, EE), 256>>>(negs, mask_n);            // 3

    static const int SMEM_BYTES = (128 * 132 + 128 * 128) * 4;
    cudaFuncSetAttribute(k_gemm, cudaFuncAttributeMaxDynamicSharedMemorySize,
                         SMEM_BYTES);
    k_gemm<<<dim3(BB / 128, QQ / 128, EE), 256, SMEM_BYTES>>>(negs, mask_n); // 4

    {
        long n = OUT_TOTAL - OUT_EASY_MASK;
        int grid = (int)((n + 1023) / 1024);
        k_fill<<<grid, 1024>>>(out + OUT_EASY_MASK, n);            // 5
    }

    k_scores<<<BB, 512>>>(smask);                                  // 6
    k_unc<<<dim3(QQ / 256, EE), 256>>>(boot);                      // 7
    k_neglogits<<<dim3(QQ / 256, BB / 8), 256>>>(query, negs, out);// 8
    k_rowstats<<<BB, 256>>>(query, key, out);                      // 9
    k_ereduce<<<QQ / 256, 256>>>();                                // 10
    k_quant<<<32, 128>>>();                                        // 11
    k_quantfin<<<1, 1>>>();                                        // 12
    k_argmax<<<BB, 256>>>(out);                                    // 13
    k_final<<<1, 256>>>(out);                                      // 14
}